// round 4
// baseline (speedup 1.0000x reference)
#include <cuda_runtime.h>

#define NB 16
#define TQ 256
#define TK 256
#define DD 256
#define FF 36
#define HH 8
#define DK 32
#define SFD 6

// Scratch (allocation-free rule: __device__ globals)
__device__ float g_Q[NB*TQ*DD];        // [b][q][h*DK+j]
__device__ float g_K[NB*TK*DD];        // [b][k][h*DK+j]
__device__ float g_E[NB*HH*TQ*TK];     // [b][h][q][k] = exp(score)
__device__ float g_HN[NB*TQ*FF*HH];    // [b][q][f][h]

// ---------------------------------------------------------------------------
// Packed fp32x2 helpers (sm_103a: FFMA2 via PTX only)
// ---------------------------------------------------------------------------
__device__ __forceinline__ float2 fma2(float2 a, float2 b, float2 c) {
    float2 d;
    asm("fma.rn.f32x2 %0, %1, %2, %3;"
        : "=l"(reinterpret_cast<unsigned long long&>(d))
        : "l"(reinterpret_cast<unsigned long long&>(a)),
          "l"(reinterpret_cast<unsigned long long&>(b)),
          "l"(reinterpret_cast<unsigned long long&>(c)));
    return d;
}
__device__ __forceinline__ float2 dup2(float s) { return make_float2(s, s); }
__device__ __forceinline__ float2 tanh2(float2 a) {
    float2 r;
    asm("tanh.approx.f32 %0, %1;" : "=f"(r.x) : "f"(a.x));
    asm("tanh.approx.f32 %0, %1;" : "=f"(r.y) : "f"(a.y));
    return r;
}

// ---------------------------------------------------------------------------
// Kernel 1: head projections, 16 rows/block, row-pairs packed into FFMA2.
// ---------------------------------------------------------------------------
__global__ void __launch_bounds__(256) proj_kernel(
        const float* __restrict__ query, const float* __restrict__ key,
        const float* __restrict__ Wq,    const float* __restrict__ Wk) {
    __shared__ __align__(16) float xst[DD][20];
    int n0 = blockIdx.x * 16;
    int which = blockIdx.y;
    const float* x = which ? key : query;
    const float* W = which ? Wk : Wq;
    int t = threadIdx.x;

#pragma unroll
    for (int r = 0; r < 16; ++r)
        xst[t][r] = x[(size_t)(n0 + r)*DD + t];
    __syncthreads();

    int h = t >> 5, j = t & 31;
    const float* w = W + h*DD*DK + j;

    float2 acc[8];
#pragma unroll
    for (int r = 0; r < 8; ++r) acc[r] = make_float2(0.f, 0.f);

#pragma unroll 8
    for (int d = 0; d < DD; ++d) {
        float2 wv = dup2(w[d*DK]);
        const float4* xr = (const float4*)&xst[d][0];
        float4 a = xr[0], b = xr[1], c = xr[2], e = xr[3];
        const float2* pa = (const float2*)&a;
        const float2* pb = (const float2*)&b;
        const float2* pc = (const float2*)&c;
        const float2* pe = (const float2*)&e;
        acc[0] = fma2(wv, pa[0], acc[0]);
        acc[1] = fma2(wv, pa[1], acc[1]);
        acc[2] = fma2(wv, pb[0], acc[2]);
        acc[3] = fma2(wv, pb[1], acc[3]);
        acc[4] = fma2(wv, pc[0], acc[4]);
        acc[5] = fma2(wv, pc[1], acc[5]);
        acc[6] = fma2(wv, pe[0], acc[6]);
        acc[7] = fma2(wv, pe[1], acc[7]);
    }

    float* out = which ? g_K : g_Q;
#pragma unroll
    for (int r = 0; r < 8; ++r) {
        out[(size_t)(n0 + 2*r    )*DD + t] = acc[r].x;
        out[(size_t)(n0 + 2*r + 1)*DD + t] = acc[r].y;
    }
}

// ---------------------------------------------------------------------------
// Kernel 2: E = exp(Q.K). Thread t owns k=t; q packed in pairs via transposed
// Q tile (LDS.128 = 4 q's) + pre-duplicated K in registers.
// ---------------------------------------------------------------------------
__global__ void __launch_bounds__(256, 2) score_kernel() {
    int b = blockIdx.x, h = blockIdx.y;
    int qb = blockIdx.z * 64;
    int t = threadIdx.x;                 // k index
    __shared__ __align__(16) float Qst[32][68];
    __shared__ __align__(16) float Ks[256][33];

    for (int i = t; i < 64*32; i += 256) {
        int q = i >> 5, j = i & 31;
        Qst[j][q] = g_Q[(size_t)(b*TQ + qb + q)*DD + h*DK + j];
    }
    for (int i = t; i < 256*32; i += 256) {
        int k = i >> 5, j = i & 31;
        Ks[k][j] = g_K[(size_t)(b*TK + k)*DD + h*DK + j];
    }
    __syncthreads();

    float2 kr2[32];
#pragma unroll
    for (int j = 0; j < 32; ++j) kr2[j] = dup2(Ks[t][j]);

    float* ep = g_E + ((size_t)(b*HH + h)*TQ + qb)*TK + t;
#pragma unroll 4
    for (int g = 0; g < 16; ++g) {       // 4 q per group
        float2 a01 = make_float2(0.f, 0.f);
        float2 a23 = make_float2(0.f, 0.f);
#pragma unroll
        for (int j = 0; j < 32; ++j) {
            float4 qv = *(const float4*)&Qst[j][g*4];
            const float2* p = (const float2*)&qv;
            a01 = fma2(p[0], kr2[j], a01);
            a23 = fma2(p[1], kr2[j], a23);
        }
        ep[(size_t)(g*4 + 0)*TK] = __expf(fminf(a01.x, 80.f));
        ep[(size_t)(g*4 + 1)*TK] = __expf(fminf(a01.y, 80.f));
        ep[(size_t)(g*4 + 2)*TK] = __expf(fminf(a23.x, 80.f));
        ep[(size_t)(g*4 + 3)*TK] = __expf(fminf(a23.y, 80.f));
    }
}

// ---------------------------------------------------------------------------
// Kernel 3: num/den = E @ [mask*value | mask], (num,den) in FFMA2 lanes.
// Es transposed [kk][q] so a q-pair of E is one LDS.64.
// Cs grouped [kk][fg][20]: each thread's 9 (mv,m) pairs = 5 aligned LDS.128.
// Per kk: 6 LDS + 18 FFMA2 -> FMA-bound.
// ---------------------------------------------------------------------------
__global__ void __launch_bounds__(128) apply_kernel(
        const float* __restrict__ value, const float* __restrict__ mask) {
    int b = blockIdx.x, h = blockIdx.y;
    int q0 = blockIdx.z * 64;
    int t = threadIdx.x;        // 128 threads
    int qg = t >> 2;            // q local = qg*2 + qq
    int fg = t & 3;             // f = fg*9 + i

    __shared__ __align__(16) float Es[32][66];      // [kk][q]
    __shared__ __align__(16) float Cs[32][4][20];   // [kk][fg][(mv,m)x9 + pad]

    float2 nd[2][9];
#pragma unroll
    for (int qq = 0; qq < 2; ++qq)
#pragma unroll
        for (int i = 0; i < 9; ++i) nd[qq][i] = make_float2(0.f, 0.f);

    const float* Ebase = g_E + ((size_t)(b*HH + h)*TQ + q0)*TK;

    for (int kt = 0; kt < TK; kt += 32) {
        __syncthreads();
        // Es fill (transposed): 64q x 32kk = 512 float4 reads, 4 per thread
#pragma unroll
        for (int r = 0; r < 4; ++r) {
            int i = t + r*128;
            int q = i >> 3;
            int kc = (i & 7) * 4;
            float4 v = *(const float4*)(Ebase + (size_t)q*TK + kt + kc);
            Es[kc+0][q] = v.x; Es[kc+1][q] = v.y;
            Es[kc+2][q] = v.z; Es[kc+3][q] = v.w;
        }
        // Cs fill: 32k x 9 float4-groups over f
        for (int i = t; i < 288; i += 128) {
            int k = i / 9;
            int c4 = (i - k*9) * 4;
            size_t base = (size_t)(b*TK + kt + k)*FF + c4;
            float4 mm = *(const float4*)(mask + base);
            float4 vv = *(const float4*)(value + base);
#pragma unroll
            for (int u = 0; u < 4; ++u) {
                int f = c4 + u;
                int g = f / 9, ii = f - g*9;
                float m = (&mm.x)[u], v = (&vv.x)[u];
                Cs[k][g][2*ii]   = m * v;
                Cs[k][g][2*ii+1] = m;
            }
        }
        __syncthreads();

#pragma unroll 4
        for (int kk = 0; kk < 32; ++kk) {
            float2 e2 = *(const float2*)&Es[kk][qg*2];
            float2 e0 = dup2(e2.x), e1 = dup2(e2.y);
            const float4* cp = (const float4*)&Cs[kk][fg][0];
            float4 c0 = cp[0], c1 = cp[1], c2 = cp[2], c3 = cp[3], c4v = cp[4];
            const float2* p0 = (const float2*)&c0;
            const float2* p1 = (const float2*)&c1;
            const float2* p2 = (const float2*)&c2;
            const float2* p3 = (const float2*)&c3;
            const float2* p4 = (const float2*)&c4v;
            float2 pr[9] = {p0[0], p0[1], p1[0], p1[1], p2[0], p2[1],
                            p3[0], p3[1], p4[0]};
#pragma unroll
            for (int i = 0; i < 9; ++i) {
                nd[0][i] = fma2(e0, pr[i], nd[0][i]);
                nd[1][i] = fma2(e1, pr[i], nd[1][i]);
            }
        }
    }

#pragma unroll
    for (int qq = 0; qq < 2; ++qq) {
        int q = q0 + qg*2 + qq;
        float* o = g_HN + (size_t)(b*TQ + q)*FF*HH + h;
#pragma unroll
        for (int i = 0; i < 9; ++i) {
            int f = fg*9 + i;
            o[(size_t)f*HH] = __fdividef(nd[qq][i].x, nd[qq][i].y);
        }
    }
}

// ---------------------------------------------------------------------------
// Kernel 4: fused epilogue. Thread owns (d, d+128) in FFMA2 lanes.
// All smem operand reads are LDS.128 (two float2 operands per issue).
// ---------------------------------------------------------------------------
__global__ void __launch_bounds__(128) epilogue_kernel(
        const float* __restrict__ Wc,  const float* __restrict__ bc,
        const float* __restrict__ Wo1, const float* __restrict__ bo1,
        const float* __restrict__ Wo2, const float* __restrict__ bo2,
        float* __restrict__ out) {
    int bq = blockIdx.x;
    int t  = threadIdx.x;       // d0 = t, d1 = t + 128
    __shared__ __align__(16) float2 hs2[FF*HH];    // duplicated pairs
    __shared__ __align__(16) float2 w12[FF*SFD];

    const float* hn = g_HN + (size_t)bq*FF*HH;
    // vectorized fills: 72 float4 (hn), 54 float4 (Wo1)
    for (int i = t; i < 72; i += 128) {
        float4 v = *(const float4*)(hn + 4*i);
        hs2[4*i+0] = dup2(v.x); hs2[4*i+1] = dup2(v.y);
        hs2[4*i+2] = dup2(v.z); hs2[4*i+3] = dup2(v.w);
    }
    if (t < 54) {
        float4 v = *(const float4*)(Wo1 + 4*t);
        w12[4*t+0] = dup2(v.x); w12[4*t+1] = dup2(v.y);
        w12[4*t+2] = dup2(v.z); w12[4*t+3] = dup2(v.w);
    }
    __syncthreads();

    int d0 = t, d1 = t + 128;
    float2 wc2[HH];
#pragma unroll
    for (int h = 0; h < HH; ++h)
        wc2[h] = make_float2(Wc[h*DD + d0], Wc[h*DD + d1]);
    float2 bc2 = make_float2(bc[d0], bc[d1]);

    float2 acc[SFD];
#pragma unroll
    for (int s = 0; s < SFD; ++s) acc[s] = dup2(bo1[s]);

#pragma unroll 4
    for (int f = 0; f < FF; ++f) {
        const float4* hp = (const float4*)&hs2[f*HH];   // f*8 float2: 16B aligned
        float2 a = bc2;
#pragma unroll
        for (int j = 0; j < 4; ++j) {
            float4 hv = hp[j];
            a = fma2(*(const float2*)&hv.x, wc2[2*j],   a);
            a = fma2(*(const float2*)&hv.z, wc2[2*j+1], a);
        }
        float2 lat = tanh2(a);
        const float4* wp = (const float4*)&w12[f*SFD];  // f*6 float2: 16B aligned
#pragma unroll
        for (int j = 0; j < 3; ++j) {
            float4 wv = wp[j];
            acc[2*j]   = fma2(lat, *(const float2*)&wv.x, acc[2*j]);
            acc[2*j+1] = fma2(lat, *(const float2*)&wv.z, acc[2*j+1]);
        }
    }

    float2 res = make_float2(bo2[d0], bo2[d1]);
#pragma unroll
    for (int s = 0; s < SFD; ++s)
        res = fma2(tanh2(acc[s]), dup2(Wo2[s]), res);

    out[(size_t)bq*DD + d0] = res.x;
    out[(size_t)bq*DD + d1] = res.y;
}

// ---------------------------------------------------------------------------
extern "C" void kernel_launch(void* const* d_in, const int* in_sizes, int n_in,
                              void* d_out, int out_size) {
    const float* query = (const float*)d_in[0];
    const float* key   = (const float*)d_in[1];
    const float* value = (const float*)d_in[2];
    const float* mask  = (const float*)d_in[3];
    const float* Wq    = (const float*)d_in[4];
    const float* Wk    = (const float*)d_in[5];
    const float* Wc    = (const float*)d_in[6];
    const float* bc    = (const float*)d_in[7];
    const float* Wo1   = (const float*)d_in[8];
    const float* bo1   = (const float*)d_in[9];
    const float* Wo2   = (const float*)d_in[10];
    const float* bo2   = (const float*)d_in[11];
    float* out = (float*)d_out;

    proj_kernel<<<dim3(NB*TQ/16, 2), 256>>>(query, key, Wq, Wk);
    score_kernel<<<dim3(NB, HH, 4), 256>>>();
    apply_kernel<<<dim3(NB, HH, 4), 128>>>(value, mask);
    epilogue_kernel<<<NB*TQ, 128>>>(Wc, bc, Wo1, bo1, Wo2, bo2, out);
}

// round 5
// speedup vs baseline: 1.0689x; 1.0689x over previous
#include <cuda_runtime.h>

#define NB 16
#define TQ 256
#define TK 256
#define DD 256
#define FF 36
#define HH 8
#define DK 32
#define SFD 6

// Scratch (allocation-free rule: __device__ globals)
__device__ float g_Q[NB*TQ*DD];        // [b][q][h*DK+j]
__device__ float g_K[NB*TK*DD];        // [b][k][h*DK+j]
__device__ float g_HN[NB*TQ*FF*HH];    // [b][q][f][h]

// ---------------------------------------------------------------------------
// Packed fp32x2 helpers (sm_103a: FFMA2 via PTX only)
// ---------------------------------------------------------------------------
__device__ __forceinline__ float2 fma2(float2 a, float2 b, float2 c) {
    float2 d;
    asm("fma.rn.f32x2 %0, %1, %2, %3;"
        : "=l"(reinterpret_cast<unsigned long long&>(d))
        : "l"(reinterpret_cast<unsigned long long&>(a)),
          "l"(reinterpret_cast<unsigned long long&>(b)),
          "l"(reinterpret_cast<unsigned long long&>(c)));
    return d;
}
__device__ __forceinline__ float2 dup2(float s) { return make_float2(s, s); }
__device__ __forceinline__ float2 tanh2(float2 a) {
    float2 r;
    asm("tanh.approx.f32 %0, %1;" : "=f"(r.x) : "f"(a.x));
    asm("tanh.approx.f32 %0, %1;" : "=f"(r.y) : "f"(a.y));
    return r;
}

// ---------------------------------------------------------------------------
// Kernel 1: head projections, 16 rows/block, row-pairs packed into FFMA2.
// ---------------------------------------------------------------------------
__global__ void __launch_bounds__(256) proj_kernel(
        const float* __restrict__ query, const float* __restrict__ key,
        const float* __restrict__ Wq,    const float* __restrict__ Wk) {
    __shared__ __align__(16) float xst[DD][20];
    int n0 = blockIdx.x * 16;
    int which = blockIdx.y;
    const float* x = which ? key : query;
    const float* W = which ? Wk : Wq;
    int t = threadIdx.x;

#pragma unroll
    for (int r = 0; r < 16; ++r)
        xst[t][r] = x[(size_t)(n0 + r)*DD + t];
    __syncthreads();

    int h = t >> 5, j = t & 31;
    const float* w = W + h*DD*DK + j;

    float2 acc[8];
#pragma unroll
    for (int r = 0; r < 8; ++r) acc[r] = make_float2(0.f, 0.f);

#pragma unroll 8
    for (int d = 0; d < DD; ++d) {
        float2 wv = dup2(w[d*DK]);
        const float4* xr = (const float4*)&xst[d][0];
        float4 a = xr[0], b = xr[1], c = xr[2], e = xr[3];
        const float2* pa = (const float2*)&a;
        const float2* pb = (const float2*)&b;
        const float2* pc = (const float2*)&c;
        const float2* pe = (const float2*)&e;
        acc[0] = fma2(wv, pa[0], acc[0]);
        acc[1] = fma2(wv, pa[1], acc[1]);
        acc[2] = fma2(wv, pb[0], acc[2]);
        acc[3] = fma2(wv, pb[1], acc[3]);
        acc[4] = fma2(wv, pc[0], acc[4]);
        acc[5] = fma2(wv, pc[1], acc[5]);
        acc[6] = fma2(wv, pe[0], acc[6]);
        acc[7] = fma2(wv, pe[1], acc[7]);
    }

    float* out = which ? g_K : g_Q;
#pragma unroll
    for (int r = 0; r < 8; ++r) {
        out[(size_t)(n0 + 2*r    )*DD + t] = acc[r].x;
        out[(size_t)(n0 + 2*r + 1)*DD + t] = acc[r].y;
    }
}

// ---------------------------------------------------------------------------
// Kernel 2 (fused score+apply): per (b, h, qtile-64) block, loop k-tiles of 32.
// Phase A: E[kk][q] = exp(Q.K) into smem. Phase B: accumulate num/den.
// No g_E round-trip (saves 268 MB of DRAM traffic).
// ---------------------------------------------------------------------------
__global__ void __launch_bounds__(128, 4) fused_attn_kernel(
        const float* __restrict__ value, const float* __restrict__ mask) {
    int b = blockIdx.x, h = blockIdx.y;
    int q0 = blockIdx.z * 64;
    int t = threadIdx.x;

    __shared__ __align__(16) float Qst[32][68];     // [j][q] transposed Q tile
    __shared__ __align__(16) float Ksd[32][66];     // [kk][2j] duplicated K tile
    __shared__ __align__(16) float Es[32][68];      // [kk][q]
    __shared__ __align__(16) float Cs[32][4][20];   // [kk][fg][(mv,m)x9 + pad]

    // Load Q tile transposed (once per block)
    for (int i = t; i < 64*32; i += 128) {
        int q = i >> 5, j = i & 31;
        Qst[j][q] = g_Q[(size_t)(b*TQ + q0 + q)*DD + h*DK + j];
    }

    // Phase B mapping
    int qg = t >> 2;            // q local = qg*2 + qq
    int fg = t & 3;             // f = fg*9 + i
    // Phase A mapping
    int kkA = t & 31;
    int qq4 = t >> 5;           // 16-q chunk

    float2 nd[2][9];
#pragma unroll
    for (int qq = 0; qq < 2; ++qq)
#pragma unroll
        for (int i = 0; i < 9; ++i) nd[qq][i] = make_float2(0.f, 0.f);

    for (int kt = 0; kt < TK; kt += 32) {
        __syncthreads();   // previous iteration's readers of Ksd/Cs done
        // K tile fill, duplicated for FFMA2: 32kk x 32j, 8 per thread
#pragma unroll
        for (int r = 0; r < 8; ++r) {
            int i = t + r*128;
            int kk = i >> 5, j = i & 31;
            float kv = g_K[(size_t)(b*TK + kt + kk)*DD + h*DK + j];
            *(float2*)&Ksd[kk][2*j] = make_float2(kv, kv);
        }
        // Cs fill: 32k x 9 float4-groups over f
        for (int i = t; i < 288; i += 128) {
            int k = i / 9;
            int c4 = (i - k*9) * 4;
            size_t base = (size_t)(b*TK + kt + k)*FF + c4;
            float4 mm = *(const float4*)(mask + base);
            float4 vv = *(const float4*)(value + base);
#pragma unroll
            for (int u = 0; u < 4; ++u) {
                int f = c4 + u;
                int g = f / 9, ii = f - g*9;
                float m = (&mm.x)[u], v = (&vv.x)[u];
                Cs[k][g][2*ii]   = m * v;
                Cs[k][g][2*ii+1] = m;
            }
        }
        __syncthreads();

        // ---- Phase A: thread owns kk = kkA, computes 16 q's (qq4*16..+15)
        {
            float2 acc2[8];
#pragma unroll
            for (int p = 0; p < 8; ++p) acc2[p] = make_float2(0.f, 0.f);
#pragma unroll
            for (int jc = 0; jc < 2; ++jc) {
                float2 kr2[16];
#pragma unroll
                for (int j = 0; j < 16; ++j)
                    kr2[j] = *(const float2*)&Ksd[kkA][2*(jc*16 + j)];
#pragma unroll
                for (int j = 0; j < 16; ++j) {
                    const float4* qp = (const float4*)&Qst[jc*16 + j][qq4*16];
#pragma unroll
                    for (int c = 0; c < 4; ++c) {
                        float4 qv = qp[c];
                        acc2[2*c]   = fma2(*(const float2*)&qv.x, kr2[j], acc2[2*c]);
                        acc2[2*c+1] = fma2(*(const float2*)&qv.z, kr2[j], acc2[2*c+1]);
                    }
                }
            }
#pragma unroll
            for (int c = 0; c < 4; ++c) {
                float4 ev;
                ev.x = __expf(fminf(acc2[2*c].x,   80.f));
                ev.y = __expf(fminf(acc2[2*c].y,   80.f));
                ev.z = __expf(fminf(acc2[2*c+1].x, 80.f));
                ev.w = __expf(fminf(acc2[2*c+1].y, 80.f));
                *(float4*)&Es[kkA][qq4*16 + 4*c] = ev;
            }
        }
        __syncthreads();

        // ---- Phase B: accumulate num/den
#pragma unroll 4
        for (int kk = 0; kk < 32; ++kk) {
            float2 e2 = *(const float2*)&Es[kk][qg*2];
            float2 e0 = dup2(e2.x), e1 = dup2(e2.y);
            const float4* cp = (const float4*)&Cs[kk][fg][0];
            float4 c0 = cp[0], c1 = cp[1], c2 = cp[2], c3 = cp[3], c4v = cp[4];
            const float2* p0 = (const float2*)&c0;
            const float2* p1 = (const float2*)&c1;
            const float2* p2 = (const float2*)&c2;
            const float2* p3 = (const float2*)&c3;
            const float2* p4 = (const float2*)&c4v;
            float2 pr[9] = {p0[0], p0[1], p1[0], p1[1], p2[0], p2[1],
                            p3[0], p3[1], p4[0]};
#pragma unroll
            for (int i = 0; i < 9; ++i) {
                nd[0][i] = fma2(e0, pr[i], nd[0][i]);
                nd[1][i] = fma2(e1, pr[i], nd[1][i]);
            }
        }
    }

#pragma unroll
    for (int qq = 0; qq < 2; ++qq) {
        int q = q0 + qg*2 + qq;
        float* o = g_HN + (size_t)(b*TQ + q)*FF*HH + h;
#pragma unroll
        for (int i = 0; i < 9; ++i) {
            int f = fg*9 + i;
            o[(size_t)f*HH] = __fdividef(nd[qq][i].x, nd[qq][i].y);
        }
    }
}

// ---------------------------------------------------------------------------
// Kernel 3: fused epilogue. Block = 2 (b,q) rows; 64 threads per row; thread
// owns 4 d's = two FFMA2 pairs. Per f: 7 LDS.128 feed 28 FFMA2 (2x R4 ratio).
// ---------------------------------------------------------------------------
__global__ void __launch_bounds__(128) epilogue_kernel(
        const float* __restrict__ Wc,  const float* __restrict__ bc,
        const float* __restrict__ Wo1, const float* __restrict__ bo1,
        const float* __restrict__ Wo2, const float* __restrict__ bo2,
        float* __restrict__ out) {
    int t    = threadIdx.x;
    int half = t >> 6;           // which bq of the pair
    int u    = t & 63;           // d base
    int bq   = 2*blockIdx.x + half;

    __shared__ __align__(16) float2 hs2[2][FF*HH];   // duplicated pairs, per bq
    __shared__ __align__(16) float2 w12[FF*SFD];

    const float* hn0 = g_HN + (size_t)(2*blockIdx.x)*FF*HH;
    for (int i = t; i < 144; i += 128) {        // 2 x 72 float4
        int which = i / 72, r = i - which*72;
        float4 v = *(const float4*)(hn0 + (size_t)which*FF*HH + 4*r);
        float2* dst = &hs2[which][4*r];
        dst[0] = dup2(v.x); dst[1] = dup2(v.y);
        dst[2] = dup2(v.z); dst[3] = dup2(v.w);
    }
    if (t < 54) {                                // 54 float4 = 216 floats
        float4 v = *(const float4*)(Wo1 + 4*t);
        w12[4*t+0] = dup2(v.x); w12[4*t+1] = dup2(v.y);
        w12[4*t+2] = dup2(v.z); w12[4*t+3] = dup2(v.w);
    }
    __syncthreads();

    int d0 = u, d1 = u + 64, d2 = u + 128, d3 = u + 192;
    float2 wcA[HH], wcB[HH];
#pragma unroll
    for (int h = 0; h < HH; ++h) {
        wcA[h] = make_float2(Wc[h*DD + d0], Wc[h*DD + d1]);
        wcB[h] = make_float2(Wc[h*DD + d2], Wc[h*DD + d3]);
    }
    float2 bcA = make_float2(bc[d0], bc[d1]);
    float2 bcB = make_float2(bc[d2], bc[d3]);

    float2 accA[SFD], accB[SFD];
#pragma unroll
    for (int s = 0; s < SFD; ++s) { accA[s] = dup2(bo1[s]); accB[s] = dup2(bo1[s]); }

    const float2* hbase = &hs2[half][0];
#pragma unroll 4
    for (int f = 0; f < FF; ++f) {
        const float4* hp = (const float4*)&hbase[f*HH];   // 8 float2, 16B aligned
        float2 aA = bcA, aB = bcB;
#pragma unroll
        for (int j = 0; j < 4; ++j) {
            float4 hv = hp[j];
            float2 lo = *(const float2*)&hv.x;
            float2 hi = *(const float2*)&hv.z;
            aA = fma2(lo, wcA[2*j],   aA);
            aA = fma2(hi, wcA[2*j+1], aA);
            aB = fma2(lo, wcB[2*j],   aB);
            aB = fma2(hi, wcB[2*j+1], aB);
        }
        float2 latA = tanh2(aA), latB = tanh2(aB);
        const float4* wp = (const float4*)&w12[f*SFD];    // 6 float2, 16B aligned
#pragma unroll
        for (int j = 0; j < 3; ++j) {
            float4 wv = wp[j];
            float2 lo = *(const float2*)&wv.x;
            float2 hi = *(const float2*)&wv.z;
            accA[2*j]   = fma2(latA, lo, accA[2*j]);
            accA[2*j+1] = fma2(latA, hi, accA[2*j+1]);
            accB[2*j]   = fma2(latB, lo, accB[2*j]);
            accB[2*j+1] = fma2(latB, hi, accB[2*j+1]);
        }
    }

    float2 resA = make_float2(bo2[d0], bo2[d1]);
    float2 resB = make_float2(bo2[d2], bo2[d3]);
#pragma unroll
    for (int s = 0; s < SFD; ++s) {
        float2 w2 = dup2(Wo2[s]);
        resA = fma2(tanh2(accA[s]), w2, resA);
        resB = fma2(tanh2(accB[s]), w2, resB);
    }

    float* o = out + (size_t)bq*DD;
    o[d0] = resA.x; o[d1] = resA.y;
    o[d2] = resB.x; o[d3] = resB.y;
}

// ---------------------------------------------------------------------------
extern "C" void kernel_launch(void* const* d_in, const int* in_sizes, int n_in,
                              void* d_out, int out_size) {
    const float* query = (const float*)d_in[0];
    const float* key   = (const float*)d_in[1];
    const float* value = (const float*)d_in[2];
    const float* mask  = (const float*)d_in[3];
    const float* Wq    = (const float*)d_in[4];
    const float* Wk    = (const float*)d_in[5];
    const float* Wc    = (const float*)d_in[6];
    const float* bc    = (const float*)d_in[7];
    const float* Wo1   = (const float*)d_in[8];
    const float* bo1   = (const float*)d_in[9];
    const float* Wo2   = (const float*)d_in[10];
    const float* bo2   = (const float*)d_in[11];
    float* out = (float*)d_out;

    proj_kernel<<<dim3(NB*TQ/16, 2), 256>>>(query, key, Wq, Wk);
    fused_attn_kernel<<<dim3(NB, HH, 4), 128>>>(value, mask);
    epilogue_kernel<<<NB*TQ/2, 128>>>(Wc, bc, Wo1, bo1, Wo2, bo2, out);
}